// round 9
// baseline (speedup 1.0000x reference)
#include <cuda_runtime.h>
#include <cstdint>

#define L 4096
#define NB 4

// Single fused kernel: 2048 blocks x 256 threads, 64 STG.128 per thread.
// Store structure identical to the proven R5 fill (every block writes a fully
// contiguous 256 KB region = 16 consecutive output rows); the only change is
// that each block decodes its seq values inline (no prep kernel, no scratch).
//
// dtype detection per block: 256 odd-word samples within the first 2048
// elements (int64 values 0..3 -> all zero; int32 -> ~surely nonzero;
// FP prob 4^-256). All reads stay within the 16 KB int32 footprint.
__global__ void __launch_bounds__(256, 8)
fused_kernel(const int* __restrict__ w,        // seq_ids as 32-bit words
             const float* __restrict__ tab,    // base_table (4x4)
             float4* __restrict__ out) {
    __shared__ int s_nonzero_odd;
    const int tid = threadIdx.x;
    const unsigned b = blockIdx.x;

    if (tid == 0) s_nonzero_odd = 0;
    __syncthreads();
    if (w[2 * tid + 1] != 0) atomicOr(&s_nonzero_odd, 1);
    __syncthreads();
    const int sh = (s_nonzero_odd == 0) ? 1 : 0;   // element x at word x<<sh

    if (b < 1024u) {
        // ---- channels 4..7: value = f(column) ----
        const int c2    = b >> 8;              // 0..3 (channel - 4)
        const int slice = b & 255;             // 16-row slice within channel

        // 16 independent seq loads (full MLP), then 4 table loads.
        int s[16];
        #pragma unroll
        for (int j = 0; j < 4; j++) {
            const int x = (((j << 8) + tid) << 2);   // first seq id of float4 j
            s[4*j+0] = w[(x    ) << sh];
            s[4*j+1] = w[(x + 1) << sh];
            s[4*j+2] = w[(x + 2) << sh];
            s[4*j+3] = w[(x + 3) << sh];
        }
        const float t0 = __ldg(&tab[ 0 + c2]);
        const float t1 = __ldg(&tab[ 4 + c2]);
        const float t2 = __ldg(&tab[ 8 + c2]);
        const float t3 = __ldg(&tab[12 + c2]);

        float4 v[4];
        #pragma unroll
        for (int j = 0; j < 4; j++) {
            float* f = (float*)&v[j];
            #pragma unroll
            for (int k = 0; k < 4; k++) {
                const int si = s[4*j+k];
                f[k] = (si == 0) ? t0 : (si == 1) ? t1 : (si == 2) ? t2 : t3;
            }
        }

        float4* p = out
                  + (((size_t)(4 + c2) << 12) + ((size_t)slice << 4)) * 1024
                  + tid;
        #pragma unroll 4
        for (int r = 0; r < 16; r++) {
            p[0]   = v[0];
            p[256] = v[1];
            p[512] = v[2];
            p[768] = v[3];
            p += 1024;                         // next consecutive row
        }
    } else {
        // ---- channels 0..3: value = f(row) ----
        const unsigned row0 = (b - 1024u) << 4;      // 16 consecutive global rows
        const int c  = (int)(row0 >> 12);            // channel 0..3
        const int i0 = (int)(row0 & 4095);

        const float t0 = __ldg(&tab[ 0 + c]);
        const float t1 = __ldg(&tab[ 4 + c]);
        const float t2 = __ldg(&tab[ 8 + c]);
        const float t3 = __ldg(&tab[12 + c]);

        // 16 broadcast seq loads up front (same address per warp -> cheap).
        int s[16];
        #pragma unroll
        for (int r = 0; r < 16; r++)
            s[r] = w[(i0 + r) << sh];

        float4* o = out + (size_t)row0 * 1024 + tid;
        #pragma unroll 4
        for (int r = 0; r < 16; r++) {
            const int si = s[r];
            const float f = (si == 0) ? t0 : (si == 1) ? t1 : (si == 2) ? t2 : t3;
            const float4 v = make_float4(f, f, f, f);
            o[0]   = v;
            o[256] = v;
            o[512] = v;
            o[768] = v;
            o += 1024;
        }
    }
}

extern "C" void kernel_launch(void* const* d_in, const int* in_sizes, int n_in,
                              void* d_out, int out_size) {
    const int*   seq        = (const int*)d_in[0];
    const float* base_table = (const float*)d_in[1];

    fused_kernel<<<2048, 256>>>(seq, base_table, (float4*)d_out);
}

// round 11
// speedup vs baseline: 1.0533x; 1.0533x over previous
#include <cuda_runtime.h>
#include <cstdint>

#define L 4096
#define NB 4

// Scratch (no device allocation allowed in kernel_launch)
__device__ float g_rows[NB * L];   // g_rows[c*L + x] = base_table[seq[x]*4 + c]

// ---------------------------------------------------------------------------
// Prep: 32 blocks x 128 threads, decode seq -> g_rows once.
// dtype detection per block: 64 odd-word samples within the first 2048
// elements (int64 values 0..3 -> all zero; int32 -> ~surely nonzero).
// Triggers programmatic completion as soon as its stores are issued.
// ---------------------------------------------------------------------------
__global__ void prep_kernel(const int* __restrict__ w,
                            const float* __restrict__ tab) {
    __shared__ int s_nonzero_odd;
    const int tid = threadIdx.x;
    const int b   = blockIdx.x;

    if (tid == 0) s_nonzero_odd = 0;
    __syncthreads();

    if (tid < 64) {
        const int k = b * 64 + tid;            // k in [0, 2048)
        if (w[2 * k + 1] != 0) atomicOr(&s_nonzero_odd, 1);
    }
    __syncthreads();
    const int sh = (s_nonzero_odd == 0) ? 1 : 0;

    const int i = b * 128 + tid;               // element index
    const int s = w[i << sh];
    #pragma unroll
    for (int c = 0; c < NB; c++) {
        g_rows[c * L + i] = tab[s * NB + c];
    }

    // Signal the dependent fill launch that this block's work is done.
    cudaTriggerProgrammaticLaunchCompletion();
}

// ---------------------------------------------------------------------------
// Fill (body identical to the proven 79.4us version): 2048 blocks x 256
// threads, 64 STG.128/thread, every block writes a contiguous 256 KB region.
// Runs its prologue concurrently with prep, then grid-dep-syncs before the
// first g_rows read.
// ---------------------------------------------------------------------------
__global__ void __launch_bounds__(256, 8)
fill_kernel(float4* __restrict__ out) {
    const int tid = threadIdx.x;
    const unsigned b = blockIdx.x;

    if (b < 1024u) {
        const int c2    = b >> 8;              // 0..3 (channel - 4)
        const int slice = b & 255;             // 16-row slice within channel

        float4* p = out
                  + (((size_t)(4 + c2) << 12) + ((size_t)slice << 4)) * 1024
                  + tid;

        cudaGridDependencySynchronize();       // wait for prep's g_rows writes

        const float4* row = (const float4*)&g_rows[c2 << 12];
        const float4 v0 = row[          tid];
        const float4 v1 = row[256     + tid];
        const float4 v2 = row[512     + tid];
        const float4 v3 = row[768     + tid];

        #pragma unroll 4
        for (int r = 0; r < 16; r++) {
            p[0]   = v0;
            p[256] = v1;
            p[512] = v2;
            p[768] = v3;
            p += 1024;                         // next consecutive row
        }
    } else {
        const unsigned row0 = (b - 1024u) << 4;   // 16 rows, global rows 0..16383
        float4* o = out + (size_t)row0 * 1024 + tid;

        cudaGridDependencySynchronize();       // wait for prep's g_rows writes

        #pragma unroll 1
        for (int r = 0; r < 16; r++) {
            const float s = g_rows[row0 + r];     // row == c*4096 + i
            const float4 v = make_float4(s, s, s, s);
            #pragma unroll
            for (int k = 0; k < 4; k++)
                o[k * 256] = v;
            o += 1024;
        }
    }
}

extern "C" void kernel_launch(void* const* d_in, const int* in_sizes, int n_in,
                              void* d_out, int out_size) {
    const int*   seq        = (const int*)d_in[0];
    const float* base_table = (const float*)d_in[1];

    prep_kernel<<<32, 128>>>(seq, base_table);

    // Programmatic dependent launch: fill starts while prep is in flight;
    // its cudaGridDependencySynchronize() waits on prep's trigger.
    cudaLaunchConfig_t cfg = {};
    cfg.gridDim  = dim3(2048);
    cfg.blockDim = dim3(256);
    cudaLaunchAttribute attr[1];
    attr[0].id = cudaLaunchAttributeProgrammaticStreamSerialization;
    attr[0].val.programmaticStreamSerializationAllowed = 1;
    cfg.attrs    = attr;
    cfg.numAttrs = 1;
    cudaLaunchKernelEx(&cfg, fill_kernel, (float4*)d_out);
}